// round 14
// baseline (speedup 1.0000x reference)
#include <cuda_runtime.h>

#define T_TOK   8192
#define DMODEL  1024
#define NEXP    8
#define DFF     4096
#define CAP     1280   // int(1.25 * 8192 / 8)
#define BK      16
#define SPLITK  4

// GEMM tile: 128(M) x 256(N), 256 threads, microtile 16(M) x 8(N), M-packed f32x2 acc
#define APAD    136                    // As row: 128 + 8 floats
#define BPAD    264                    // Bs row: 256 + 8 floats
#define AS_FLOATS (2 * BK * APAD)      // 4352
#define BS_STAGE  (BK * BPAD)          // 4224
#define SMEM_TOT  ((AS_FLOATS + 3 * BS_STAGE) * 4)   // 68096 B -> dynamic smem

typedef unsigned int u32;
typedef unsigned long long ull;

// ---------------- scratch (device globals; no allocation) ----------------
__device__ float g_disp[(size_t)NEXP * CAP * DMODEL];              // 40 MB
__device__ float g_h   [(size_t)NEXP * CAP * DFF];                 // 167 MB
__device__ float g_part[(size_t)SPLITK * NEXP * CAP * DMODEL];     // 160 MB
__device__ int   g_idx [T_TOK];
__device__ float g_gate[T_TOK];
__device__ int   g_slot[T_TOK];
__device__ int   g_cnt [NEXP];

// ---------------- packed f32x2 + async-copy helpers ----------------
__device__ __forceinline__ ull pk(float x, float y) {
    ull r; asm("mov.b64 %0, {%1, %2};" : "=l"(r) : "f"(x), "f"(y)); return r;
}
__device__ __forceinline__ void upk(ull v, float& x, float& y) {
    asm("mov.b64 {%0, %1}, %2;" : "=f"(x), "=f"(y) : "l"(v));
}
__device__ __forceinline__ ull ffma2(ull a, ull b, ull c) {
    ull d; asm("fma.rn.f32x2 %0, %1, %2, %3;" : "=l"(d) : "l"(a), "l"(b), "l"(c)); return d;
}
__device__ __forceinline__ u32 smem_u32(const void* p) {
    u32 a; asm("{ .reg .u64 t; cvta.to.shared.u64 t, %1; cvt.u32.u64 %0, t; }" : "=r"(a) : "l"(p));
    return a;
}
__device__ __forceinline__ void cpa16(u32 s, const void* g) {
    asm volatile("cp.async.cg.shared.global [%0], [%1], 16;" :: "r"(s), "l"(g));
}
__device__ __forceinline__ void cpa_commit() { asm volatile("cp.async.commit_group;" ::: "memory"); }
__device__ __forceinline__ void cpa_wait1()  { asm volatile("cp.async.wait_group 1;" ::: "memory"); }
__device__ __forceinline__ void cpa_wait0()  { asm volatile("cp.async.wait_group 0;" ::: "memory"); }

// ---------------- 1. gating ----------------
__global__ void gate_kernel(const float* __restrict__ x, const float* __restrict__ wg) {
    __shared__ float wgT[NEXP][DMODEL];
    int tid = threadIdx.x;
    for (int i = tid; i < DMODEL * NEXP; i += 256)
        wgT[i & 7][i >> 3] = wg[i];
    __syncthreads();
    int warp = tid >> 5, lane = tid & 31;
    int t = blockIdx.x * 8 + warp;
    const float* xr = x + (size_t)t * DMODEL;
    float acc[NEXP];
#pragma unroll
    for (int e = 0; e < NEXP; e++) acc[e] = 0.0f;
    for (int m = lane; m < DMODEL; m += 32) {
        float xv = xr[m];
#pragma unroll
        for (int e = 0; e < NEXP; e++) acc[e] += xv * wgT[e][m];
    }
#pragma unroll
    for (int e = 0; e < NEXP; e++)
#pragma unroll
        for (int o = 16; o; o >>= 1)
            acc[e] += __shfl_xor_sync(0xffffffffu, acc[e], o);
    if (lane == 0) {
        float mx = acc[0]; int a = 0;
#pragma unroll
        for (int e = 1; e < NEXP; e++)
            if (acc[e] > mx) { mx = acc[e]; a = e; }   // first-max, matches jnp.argmax
        float s = 0.0f;
#pragma unroll
        for (int e = 0; e < NEXP; e++) s += expf(acc[e] - mx);
        g_idx[t]  = a;
        g_gate[t] = 1.0f / s;
    }
}

// ---------------- 2. queue positions + per-expert counts ----------------
__global__ void scan_kernel() {
    __shared__ int wsum[8][NEXP];
    __shared__ int wbase[8][NEXP];
    int tid = threadIdx.x, wid = tid >> 5, lane = tid & 31;
    int loc[32];
    const int4* gp = (const int4*)(g_idx + tid * 32);
#pragma unroll
    for (int v = 0; v < 8; v++) {
        int4 q = gp[v];
        loc[v * 4 + 0] = q.x; loc[v * 4 + 1] = q.y;
        loc[v * 4 + 2] = q.z; loc[v * 4 + 3] = q.w;
    }
    int cnt[NEXP];
#pragma unroll
    for (int e = 0; e < NEXP; e++) cnt[e] = 0;
#pragma unroll
    for (int j = 0; j < 32; j++) cnt[loc[j]]++;
    int excl[NEXP];
#pragma unroll
    for (int e = 0; e < NEXP; e++) {
        int inc = cnt[e];
#pragma unroll
        for (int off = 1; off < 32; off <<= 1) {
            int n = __shfl_up_sync(0xffffffffu, inc, off);
            if (lane >= off) inc += n;
        }
        excl[e] = inc - cnt[e];
        if (lane == 31) wsum[wid][e] = inc;
    }
    __syncthreads();
    if (tid == 0) {
#pragma unroll
        for (int e = 0; e < NEXP; e++) {
            int run = 0;
            for (int w = 0; w < 8; w++) { wbase[w][e] = run; run += wsum[w][e]; }
            g_cnt[e] = (run < CAP) ? run : CAP;
        }
    }
    __syncthreads();
    int pos[NEXP];
#pragma unroll
    for (int e = 0; e < NEXP; e++) pos[e] = wbase[wid][e] + excl[e];
#pragma unroll
    for (int j = 0; j < 32; j++) {
        int e = loc[j];
        int p = pos[e]++;
        g_slot[tid * 32 + j] = (p < CAP) ? p : -1;
    }
}

// ---------------- 3. dispatch (gather tokens into [E,C,M]) ----------------
__global__ void gather_kernel(const float* __restrict__ x) {
    int t = blockIdx.x;
    int sl = g_slot[t];
    if (sl < 0) return;
    int e = g_idx[t];
    const float4* src = (const float4*)(x + (size_t)t * DMODEL);
    float4* dst = (float4*)(g_disp + ((size_t)e * CAP + sl) * DMODEL);
    dst[threadIdx.x] = src[threadIdx.x];
}

// ---------------- 4. per-expert SGEMM: 128x256 tile, 16x8 microtile ----------------
// Raw LDS bytes: 96 B per 128 MACs per thread per kk (0.75 B/MAC) -> fma-bound.
// acc[m][n] = packed M-pair; A pairs straight from SMEM (zero MOVs), B duplicated (8 pk).
// As double-buffered (reg-staged), Bs triple-buffered (cp.async), one barrier per chunk.
template<int N, int LDA, bool RELU, int PHASE>
__global__ __launch_bounds__(256, 1)
void sgemm_kernel(const float* __restrict__ Bw, const float* __restrict__ biasb) {
    extern __shared__ __align__(128) float smem[];
    float* Asf = smem;                       // [2][BK][APAD]
    float* Bsf = smem + AS_FLOATS;           // [3][BK][BPAD]

    constexpr int KD = 1024;                 // K depth per slab
    const int z  = blockIdx.z;
    const int e  = (PHASE == 1) ? z : (z & 7);
    const int ks = (PHASE == 1) ? 0 : (z >> 3);
    const int bm = blockIdx.y * 128;
    if (bm >= g_cnt[e]) return;              // expert under-filled: skip

    const float* A;
    float* Cc;
    if (PHASE == 1) {
        A  = g_disp + (size_t)e * CAP * DMODEL;
        Cc = g_h    + (size_t)e * CAP * DFF;
    } else {
        A  = g_h    + (size_t)e * CAP * DFF + (size_t)ks * KD;
        Cc = g_part + (size_t)z * CAP * DMODEL;
    }
    const float* B    = (PHASE == 1) ? (Bw + (size_t)e * KD * N)
                                     : (Bw + (size_t)e * DFF * N + (size_t)ks * KD * N);
    const float* bias = biasb + (size_t)e * N;

    const int bn = blockIdx.x * 256;
    const int tid = threadIdx.x;
    const int wid = tid >> 5, lane = tid & 31;
    // thread grid 8 (M) x 32 (N): warps 4 wy x 2 wx; lanes 2 lty x 16 ltx
    const int ty = (wid >> 1) * 2 + (lane >> 4);   // 0..7   (16 M rows each)
    const int tx = (wid & 1) * 16 + (lane & 15);   // 0..31  (8 N cols each)
    constexpr int NCH = KD / BK;

    const int ar  = tid >> 1;                // A: 2 threads per row, 8 floats each
    const int ak0 = (tid & 1) * 8;
    const float* Aptr = A + (size_t)(bm + ar) * LDA + ak0;

    const int bk0   = tid >> 4;              // B: 16 threads per k-row, 64B each
    const int bcol0 = (tid & 15) * 16;
    const float* Bptr = B + (size_t)bk0 * N + bn + bcol0;
    u32 bs_st[3] = { smem_u32(&Bsf[0 * BS_STAGE + bk0 * BPAD + bcol0]),
                     smem_u32(&Bsf[1 * BS_STAGE + bk0 * BPAD + bcol0]),
                     smem_u32(&Bsf[2 * BS_STAGE + bk0 * BPAD + bcol0]) };

    // prologue: A(0), A(1) in regs; B(0), B(1) in flight
    float4 areg[2][2];
    areg[0][0] = *(const float4*)(Aptr);
    areg[0][1] = *(const float4*)(Aptr + 4);
#pragma unroll
    for (int q = 0; q < 4; q++) cpa16(bs_st[0] + q * 16, Bptr + q * 4);
    cpa_commit();
    areg[1][0] = *(const float4*)(Aptr + BK);
    areg[1][1] = *(const float4*)(Aptr + BK + 4);
#pragma unroll
    for (int q = 0; q < 4; q++) cpa16(bs_st[1] + q * 16, Bptr + (size_t)BK * N + q * 4);
    cpa_commit();

    ull acc[8][8];   // acc[m][n] = (C[ty*16+2m][tx*8+n], C[ty*16+2m+1][tx*8+n])
#pragma unroll
    for (int i = 0; i < 8; i++)
#pragma unroll
        for (int j = 0; j < 8; j++) acc[i][j] = 0ull;

#pragma unroll 1
    for (int c = 0; c < NCH; c++) {
        const int sa = c & 1;
        // store A chunk c (in regs) transposed into As[sa]; safe pre-barrier
        float* abuf = Asf + sa * (BK * APAD);
#pragma unroll
        for (int q = 0; q < 2; q++) {
            float4 v = areg[sa][q];
            int kq = ak0 + q * 4;
            abuf[(kq + 0) * APAD + ar] = v.x;
            abuf[(kq + 1) * APAD + ar] = v.y;
            abuf[(kq + 2) * APAD + ar] = v.z;
            abuf[(kq + 3) * APAD + ar] = v.w;
        }
        if (c + 1 < NCH) cpa_wait1(); else cpa_wait0();   // B(c) landed
        __syncthreads();                                  // As[sa] + Bs[c%3] visible
        const float* bbuf = Bsf + (c % 3) * BS_STAGE;
#pragma unroll
        for (int kk = 0; kk < BK; kk++) {
            // A: 16 M-values as 8 natural packed pairs (zero MOVs)
            const ull* arow = (const ull*)(abuf + kk * APAD + ty * 16);
            ulonglong2 A0 = *(const ulonglong2*)(arow);
            ulonglong2 A1 = *(const ulonglong2*)(arow + 2);
            ulonglong2 A2 = *(const ulonglong2*)(arow + 4);
            ulonglong2 A3 = *(const ulonglong2*)(arow + 6);
            ull am[8] = { A0.x, A0.y, A1.x, A1.y, A2.x, A2.y, A3.x, A3.y };
            // B: 8 N-values, duplicated
            const float* brow = bbuf + kk * BPAD + tx * 8;
            float4 b0 = *(const float4*)(brow);
            float4 b1 = *(const float4*)(brow + 4);
            ull bp[8] = { pk(b0.x, b0.x), pk(b0.y, b0.y), pk(b0.z, b0.z), pk(b0.w, b0.w),
                          pk(b1.x, b1.x), pk(b1.y, b1.y), pk(b1.z, b1.z), pk(b1.w, b1.w) };
#pragma unroll
            for (int m = 0; m < 8; m++)
#pragma unroll
                for (int n = 0; n < 8; n++)
                    acc[m][n] = ffma2(am[m], bp[n], acc[m][n]);
        }
        // post-compute: prefetch chunk c+2 (A -> regs, B -> Bs[(c+2)%3])
        if (c + 2 < NCH) {
            const float* ap2 = Aptr + (size_t)(c + 2) * BK;
            areg[sa][0] = *(const float4*)(ap2);
            areg[sa][1] = *(const float4*)(ap2 + 4);
            const float* bp2g = Bptr + (size_t)(c + 2) * BK * N;
            u32 bss = bs_st[(c + 2) % 3];
#pragma unroll
            for (int q = 0; q < 4; q++) cpa16(bss + q * 16, bp2g + q * 4);
            cpa_commit();
        }
    }

    // epilogue: rows bm+ty*16+(0..15), cols bn+tx*8+(0..7)
    float bv[8];
    if (PHASE == 1) {
#pragma unroll
        for (int j = 0; j < 8; j++) bv[j] = bias[bn + tx * 8 + j];
    }
#pragma unroll
    for (int m = 0; m < 8; m++) {
        float lo[8], hi[8];
#pragma unroll
        for (int n = 0; n < 8; n++) upk(acc[m][n], lo[n], hi[n]);
        if (PHASE == 1) {
#pragma unroll
            for (int n = 0; n < 8; n++) {
                lo[n] = fmaxf(lo[n] + bv[n], 0.0f);
                hi[n] = fmaxf(hi[n] + bv[n], 0.0f);
            }
        }
        float* c0 = Cc + (size_t)(bm + ty * 16 + 2 * m) * N + bn + tx * 8;
        *(float4*)c0           = make_float4(lo[0], lo[1], lo[2], lo[3]);
        *(float4*)(c0 + 4)     = make_float4(lo[4], lo[5], lo[6], lo[7]);
        *(float4*)(c0 + N)     = make_float4(hi[0], hi[1], hi[2], hi[3]);
        *(float4*)(c0 + N + 4) = make_float4(hi[4], hi[5], hi[6], hi[7]);
    }
}

// ---------------- 5. combine (+ split-K reduction, fixed order -> deterministic) ----------------
__global__ void combine_kernel(const float* __restrict__ b2, float* __restrict__ out) {
    int t = blockIdx.x;
    int sl = g_slot[t];
    float4* o = (float4*)(out + (size_t)t * DMODEL);
    int i = threadIdx.x;
    if (sl < 0) {
        o[i] = make_float4(0.f, 0.f, 0.f, 0.f);
        return;
    }
    float g = g_gate[t];
    int e = g_idx[t];
    const size_t stride = (size_t)NEXP * CAP * DMODEL;
    const float* p = g_part + ((size_t)e * CAP + sl) * DMODEL + i * 4;
    float4 s = *(const float4*)p;
#pragma unroll
    for (int ks = 1; ks < SPLITK; ks++) {
        float4 v = *(const float4*)(p + ks * stride);
        s.x += v.x; s.y += v.y; s.z += v.z; s.w += v.w;
    }
    float4 b = *(const float4*)(b2 + (size_t)e * DMODEL + i * 4);
    o[i] = make_float4((s.x + b.x) * g, (s.y + b.y) * g,
                       (s.z + b.z) * g, (s.w + b.w) * g);
}

// ---------------- launch ----------------
extern "C" void kernel_launch(void* const* d_in, const int* in_sizes, int n_in,
                              void* d_out, int out_size) {
    const float* x  = (const float*)d_in[0];   // [4,2048,1024]
    const float* wg = (const float*)d_in[1];   // [1024,8]
    const float* w1 = (const float*)d_in[2];   // [8,1024,4096]
    const float* b1 = (const float*)d_in[3];   // [8,4096]
    const float* w2 = (const float*)d_in[4];   // [8,4096,1024]
    const float* b2 = (const float*)d_in[5];   // [8,1024]
    float* out = (float*)d_out;                // [4,2048,1024]

    cudaFuncSetAttribute(sgemm_kernel<DFF, DMODEL, true, 1>,
                         cudaFuncAttributeMaxDynamicSharedMemorySize, SMEM_TOT);
    cudaFuncSetAttribute(sgemm_kernel<DMODEL, DFF, false, 2>,
                         cudaFuncAttributeMaxDynamicSharedMemorySize, SMEM_TOT);

    gate_kernel<<<T_TOK / 8, 256>>>(x, wg);
    scan_kernel<<<1, 256>>>();
    gather_kernel<<<T_TOK, 256>>>(x);
    // GEMM1: full K=1024 per block, tile 128x256
    sgemm_kernel<DFF, DMODEL, true, 1>
        <<<dim3(DFF / 256, CAP / 128, NEXP), 256, SMEM_TOT>>>(w1, b1);
    // GEMM2: split-K=4 slabs of 1024 -> partials, tile 128x256
    sgemm_kernel<DMODEL, DFF, false, 2>
        <<<dim3(DMODEL / 256, CAP / 128, NEXP * SPLITK), 256, SMEM_TOT>>>(w2, nullptr);
    combine_kernel<<<T_TOK, 256>>>(b2, out);
}

// round 16
// speedup vs baseline: 1.0610x; 1.0610x over previous
#include <cuda_runtime.h>

#define T_TOK   8192
#define DMODEL  1024
#define NEXP    8
#define DFF     4096
#define CAP     1280   // int(1.25 * 8192 / 8)
#define BK      16
#define PADW    160
#define SPLITK  4

typedef unsigned int u32;
typedef unsigned long long ull;

// ---------------- scratch (device globals; no allocation) ----------------
__device__ float g_disp[(size_t)NEXP * CAP * DMODEL];              // 40 MB
__device__ float g_h   [(size_t)NEXP * CAP * DFF];                 // 167 MB
__device__ float g_part[(size_t)SPLITK * NEXP * CAP * DMODEL];     // 160 MB
__device__ int   g_idx [T_TOK];
__device__ float g_gate[T_TOK];
__device__ int   g_slot[T_TOK];
__device__ int   g_cnt [NEXP];

// ---------------- packed f32x2 + async-copy helpers ----------------
__device__ __forceinline__ ull pk(float x, float y) {
    ull r; asm("mov.b64 %0, {%1, %2};" : "=l"(r) : "f"(x), "f"(y)); return r;
}
__device__ __forceinline__ void upk(ull v, float& x, float& y) {
    asm("mov.b64 {%0, %1}, %2;" : "=f"(x), "=f"(y) : "l"(v));
}
__device__ __forceinline__ ull ffma2(ull a, ull b, ull c) {
    ull d; asm("fma.rn.f32x2 %0, %1, %2, %3;" : "=l"(d) : "l"(a), "l"(b), "l"(c)); return d;
}
__device__ __forceinline__ u32 smem_u32(const void* p) {
    u32 a; asm("{ .reg .u64 t; cvta.to.shared.u64 t, %1; cvt.u32.u64 %0, t; }" : "=r"(a) : "l"(p));
    return a;
}
__device__ __forceinline__ void cpa16(u32 s, const void* g) {
    asm volatile("cp.async.cg.shared.global [%0], [%1], 16;" :: "r"(s), "l"(g));
}
__device__ __forceinline__ void cpa_commit() { asm volatile("cp.async.commit_group;" ::: "memory"); }
__device__ __forceinline__ void cpa_wait1()  { asm volatile("cp.async.wait_group 1;" ::: "memory"); }
__device__ __forceinline__ void cpa_wait0()  { asm volatile("cp.async.wait_group 0;" ::: "memory"); }

// ---------------- 1. gating ----------------
__global__ void gate_kernel(const float* __restrict__ x, const float* __restrict__ wg) {
    __shared__ float wgT[NEXP][DMODEL];
    int tid = threadIdx.x;
    for (int i = tid; i < DMODEL * NEXP; i += 256)
        wgT[i & 7][i >> 3] = wg[i];
    __syncthreads();
    int warp = tid >> 5, lane = tid & 31;
    int t = blockIdx.x * 8 + warp;
    const float* xr = x + (size_t)t * DMODEL;
    float acc[NEXP];
#pragma unroll
    for (int e = 0; e < NEXP; e++) acc[e] = 0.0f;
    for (int m = lane; m < DMODEL; m += 32) {
        float xv = xr[m];
#pragma unroll
        for (int e = 0; e < NEXP; e++) acc[e] += xv * wgT[e][m];
    }
#pragma unroll
    for (int e = 0; e < NEXP; e++)
#pragma unroll
        for (int o = 16; o; o >>= 1)
            acc[e] += __shfl_xor_sync(0xffffffffu, acc[e], o);
    if (lane == 0) {
        float mx = acc[0]; int a = 0;
#pragma unroll
        for (int e = 1; e < NEXP; e++)
            if (acc[e] > mx) { mx = acc[e]; a = e; }   // first-max, matches jnp.argmax
        float s = 0.0f;
#pragma unroll
        for (int e = 0; e < NEXP; e++) s += expf(acc[e] - mx);
        g_idx[t]  = a;
        g_gate[t] = 1.0f / s;
    }
}

// ---------------- 2. queue positions + per-expert counts ----------------
__global__ void scan_kernel() {
    __shared__ int wsum[8][NEXP];
    __shared__ int wbase[8][NEXP];
    int tid = threadIdx.x, wid = tid >> 5, lane = tid & 31;
    int loc[32];
    const int4* gp = (const int4*)(g_idx + tid * 32);
#pragma unroll
    for (int v = 0; v < 8; v++) {
        int4 q = gp[v];
        loc[v * 4 + 0] = q.x; loc[v * 4 + 1] = q.y;
        loc[v * 4 + 2] = q.z; loc[v * 4 + 3] = q.w;
    }
    int cnt[NEXP];
#pragma unroll
    for (int e = 0; e < NEXP; e++) cnt[e] = 0;
#pragma unroll
    for (int j = 0; j < 32; j++) cnt[loc[j]]++;
    int excl[NEXP];
#pragma unroll
    for (int e = 0; e < NEXP; e++) {
        int inc = cnt[e];
#pragma unroll
        for (int off = 1; off < 32; off <<= 1) {
            int n = __shfl_up_sync(0xffffffffu, inc, off);
            if (lane >= off) inc += n;
        }
        excl[e] = inc - cnt[e];
        if (lane == 31) wsum[wid][e] = inc;
    }
    __syncthreads();
    if (tid == 0) {
#pragma unroll
        for (int e = 0; e < NEXP; e++) {
            int run = 0;
            for (int w = 0; w < 8; w++) { wbase[w][e] = run; run += wsum[w][e]; }
            g_cnt[e] = (run < CAP) ? run : CAP;
        }
    }
    __syncthreads();
    int pos[NEXP];
#pragma unroll
    for (int e = 0; e < NEXP; e++) pos[e] = wbase[wid][e] + excl[e];
#pragma unroll
    for (int j = 0; j < 32; j++) {
        int e = loc[j];
        int p = pos[e]++;
        g_slot[tid * 32 + j] = (p < CAP) ? p : -1;
    }
}

// ---------------- 3. dispatch (gather tokens into [E,C,M]) ----------------
__global__ void gather_kernel(const float* __restrict__ x) {
    int t = blockIdx.x;
    int sl = g_slot[t];
    if (sl < 0) return;
    int e = g_idx[t];
    const float4* src = (const float4*)(x + (size_t)t * DMODEL);
    float4* dst = (float4*)(g_disp + ((size_t)e * CAP + sl) * DMODEL);
    dst[threadIdx.x] = src[threadIdx.x];
}

// ---------------- 4. per-expert SGEMM: warp-uniform A (broadcast LDS) ----------------
// 128x128 tile, K slab 1024, 256 threads, 16(M)x4(N) microtile, M-packed f32x2 acc.
// Warp shape 1 x 32: ty = wid (warp-uniform A row window -> LDS full broadcast, 1 wf),
// tx = lane (B-frag 512B consecutive per warp, 4 wf). 8 wf/kk/warp total.
// As double-buffered (reg-staged), Bs triple-buffered (cp.async), one barrier per chunk.
template<int N, int LDA, bool RELU, int PHASE>
__global__ __launch_bounds__(256, 2)
void sgemm_kernel(const float* __restrict__ Bw, const float* __restrict__ biasb) {
    __shared__ __align__(128) float As[2][BK][PADW];
    __shared__ __align__(128) float Bs[3][BK][PADW];

    constexpr int KD = 1024;             // K depth per slab
    const int z  = blockIdx.z;
    const int e  = (PHASE == 1) ? z : (z & 7);
    const int ks = (PHASE == 1) ? 0 : (z >> 3);
    const int bm = blockIdx.y * 128;
    if (bm >= g_cnt[e]) return;          // expert under-filled: skip

    const float* A;
    float* Cc;
    if (PHASE == 1) {
        A  = g_disp + (size_t)e * CAP * DMODEL;
        Cc = g_h    + (size_t)e * CAP * DFF;
    } else {
        A  = g_h    + (size_t)e * CAP * DFF + (size_t)ks * KD;
        Cc = g_part + (size_t)z * CAP * DMODEL;
    }
    const float* B    = (PHASE == 1) ? (Bw + (size_t)e * KD * N)
                                     : (Bw + (size_t)e * DFF * N + (size_t)ks * KD * N);
    const float* bias = biasb + (size_t)e * N;

    const int bn = blockIdx.x * 128;
    const int tid = threadIdx.x;
    const int wid = tid >> 5, lane = tid & 31;
    // warp-uniform M mapping: each warp owns 16 M rows; lanes spread across all 128 N cols
    const int ty = wid;      // 0..7  (16 M rows each; A-frag address uniform per warp)
    const int tx = lane;     // 0..31 (4 N cols each)
    constexpr int NCH = KD / BK;

    const int ar  = tid >> 1;
    const int ak0 = (tid & 1) * 8;
    const float* Aptr = A + (size_t)(bm + ar) * LDA + ak0;

    const int bk0  = tid >> 4;
    const int bseg = (tid * 2) & 31;
    const float* Bptr = B + (size_t)bk0 * N + bn + bseg * 4;
    u32 bs_st[3] = { smem_u32(&Bs[0][bk0][bseg * 4]),
                     smem_u32(&Bs[1][bk0][bseg * 4]),
                     smem_u32(&Bs[2][bk0][bseg * 4]) };

    // prologue: A(0), A(1) in regs; B(0), B(1) in flight
    float4 areg[2][2];
    areg[0][0] = *(const float4*)(Aptr);
    areg[0][1] = *(const float4*)(Aptr + 4);
    cpa16(bs_st[0],      Bptr);
    cpa16(bs_st[0] + 16, Bptr + 4);
    cpa_commit();
    areg[1][0] = *(const float4*)(Aptr + BK);
    areg[1][1] = *(const float4*)(Aptr + BK + 4);
    cpa16(bs_st[1],      Bptr + (size_t)BK * N);
    cpa16(bs_st[1] + 16, Bptr + (size_t)BK * N + 4);
    cpa_commit();

    ull acc[8][4];   // acc[m][n] = (C[ty*16+2m][tx*4+n], C[ty*16+2m+1][tx*4+n])
#pragma unroll
    for (int i = 0; i < 8; i++)
#pragma unroll
        for (int j = 0; j < 4; j++) acc[i][j] = 0ull;

#pragma unroll 1
    for (int c = 0; c < NCH; c++) {
        const int sa = c & 1;
        // store A chunk c (in regs) transposed into As[sa]; safe pre-barrier
        // (readers of As[sa] finished before the previous barrier).
#pragma unroll
        for (int q = 0; q < 2; q++) {
            float4 v = areg[sa][q];
            int kq = ak0 + q * 4;
            As[sa][kq + 0][ar] = v.x;
            As[sa][kq + 1][ar] = v.y;
            As[sa][kq + 2][ar] = v.z;
            As[sa][kq + 3][ar] = v.w;
        }
        if (c + 1 < NCH) cpa_wait1(); else cpa_wait0();   // B(c) landed
        __syncthreads();                                  // As[sa] + Bs[c%3] visible
        const int sb = c % 3;
#pragma unroll
        for (int kk = 0; kk < BK; kk++) {
            // A: 16 M-values as 8 natural packed pairs; address uniform across the
            // warp -> full LDS broadcast (1 wavefront per LDS.128)
            const ull* arow = (const ull*)&As[sa][kk][ty * 16];
            ulonglong2 A0 = *(const ulonglong2*)(arow);
            ulonglong2 A1 = *(const ulonglong2*)(arow + 2);
            ulonglong2 A2 = *(const ulonglong2*)(arow + 4);
            ulonglong2 A3 = *(const ulonglong2*)(arow + 6);
            ull am[8] = { A0.x, A0.y, A1.x, A1.y, A2.x, A2.y, A3.x, A3.y };
            // B: 4 N-values, duplicated (4 pk); lane-consecutive float4 -> 4 wf/warp
            float4 b = *(const float4*)&Bs[sb][kk][tx * 4];
            ull bp[4] = { pk(b.x, b.x), pk(b.y, b.y), pk(b.z, b.z), pk(b.w, b.w) };
#pragma unroll
            for (int m = 0; m < 8; m++) {
                acc[m][0] = ffma2(am[m], bp[0], acc[m][0]);
                acc[m][1] = ffma2(am[m], bp[1], acc[m][1]);
                acc[m][2] = ffma2(am[m], bp[2], acc[m][2]);
                acc[m][3] = ffma2(am[m], bp[3], acc[m][3]);
            }
        }
        // post-compute: prefetch chunk c+2 (A -> regs, B -> Bs[(c+2)%3]).
        if (c + 2 < NCH) {
            const float* ap2 = Aptr + (size_t)(c + 2) * BK;
            areg[sa][0] = *(const float4*)(ap2);
            areg[sa][1] = *(const float4*)(ap2 + 4);
            const float* bp2g = Bptr + (size_t)(c + 2) * BK * N;
            u32 bss = bs_st[(c + 2) % 3];
            cpa16(bss,      bp2g);
            cpa16(bss + 16, bp2g + 4);
            cpa_commit();
        }
    }

    // epilogue: each thread owns rows bm+ty*16+(0..15), cols bn+tx*4+(0..3)
    float bv[4];
    if (PHASE == 1) {
#pragma unroll
        for (int j = 0; j < 4; j++) bv[j] = bias[bn + tx * 4 + j];
    }
#pragma unroll
    for (int m = 0; m < 8; m++) {
        float lo[4], hi[4];
#pragma unroll
        for (int n = 0; n < 4; n++) upk(acc[m][n], lo[n], hi[n]);
        if (PHASE == 1) {
#pragma unroll
            for (int n = 0; n < 4; n++) {
                lo[n] = fmaxf(lo[n] + bv[n], 0.0f);
                hi[n] = fmaxf(hi[n] + bv[n], 0.0f);
            }
        }
        float* c0 = Cc + (size_t)(bm + ty * 16 + 2 * m) * N + bn + tx * 4;
        *(float4*)c0       = make_float4(lo[0], lo[1], lo[2], lo[3]);
        *(float4*)(c0 + N) = make_float4(hi[0], hi[1], hi[2], hi[3]);
    }
}

// ---------------- 5. combine (+ split-K reduction, fixed order -> deterministic) ----------------
__global__ void combine_kernel(const float* __restrict__ b2, float* __restrict__ out) {
    int t = blockIdx.x;
    int sl = g_slot[t];
    float4* o = (float4*)(out + (size_t)t * DMODEL);
    int i = threadIdx.x;
    if (sl < 0) {
        o[i] = make_float4(0.f, 0.f, 0.f, 0.f);
        return;
    }
    float g = g_gate[t];
    int e = g_idx[t];
    const size_t stride = (size_t)NEXP * CAP * DMODEL;
    const float* p = g_part + ((size_t)e * CAP + sl) * DMODEL + i * 4;
    float4 s = *(const float4*)p;
#pragma unroll
    for (int ks = 1; ks < SPLITK; ks++) {
        float4 v = *(const float4*)(p + ks * stride);
        s.x += v.x; s.y += v.y; s.z += v.z; s.w += v.w;
    }
    float4 b = *(const float4*)(b2 + (size_t)e * DMODEL + i * 4);
    o[i] = make_float4((s.x + b.x) * g, (s.y + b.y) * g,
                       (s.z + b.z) * g, (s.w + b.w) * g);
}

// ---------------- launch ----------------
extern "C" void kernel_launch(void* const* d_in, const int* in_sizes, int n_in,
                              void* d_out, int out_size) {
    const float* x  = (const float*)d_in[0];   // [4,2048,1024]
    const float* wg = (const float*)d_in[1];   // [1024,8]
    const float* w1 = (const float*)d_in[2];   // [8,1024,4096]
    const float* b1 = (const float*)d_in[3];   // [8,4096]
    const float* w2 = (const float*)d_in[4];   // [8,4096,1024]
    const float* b2 = (const float*)d_in[5];   // [8,1024]
    float* out = (float*)d_out;                // [4,2048,1024]

    gate_kernel<<<T_TOK / 8, 256>>>(x, wg);
    scan_kernel<<<1, 256>>>();
    gather_kernel<<<T_TOK, 256>>>(x);
    // GEMM1: full K=1024 per block
    sgemm_kernel<DFF, DMODEL, true, 1>
        <<<dim3(DFF / 128, CAP / 128, NEXP), 256>>>(w1, b1);
    // GEMM2: split-K=4 slabs of 1024 -> partials
    sgemm_kernel<DMODEL, DFF, false, 2>
        <<<dim3(DMODEL / 128, CAP / 128, NEXP * SPLITK), 256>>>(w2, nullptr);
    combine_kernel<<<T_TOK, 256>>>(b2, out);
}